// round 2
// baseline (speedup 1.0000x reference)
#include <cuda_runtime.h>

#define Bn   128
#define Tn   50
#define MI   32
#define En   128
#define Dn   144
#define G3   432
#define KD   144
#define CREG 96
#define KS   48   // KD - CREG

// scratch (static device globals; no runtime allocation)
__device__ float g_seq [Bn*Tn*Dn];   // embedded sequence  (6400,144)
__device__ float g_gi  [Bn*Tn*G3];   // input gates        (6400,432)
__device__ float g_hseq[Bn*Tn*Dn];   // all hidden states  (6400,144)

// ---------------------------------------------------------------------------
// 1) basket embedding: mean-pool item embeddings + wchange flag vector
// ---------------------------------------------------------------------------
__global__ void embed_kernel(const int* __restrict__ x,
                             const float* __restrict__ encode_w,
                             const float* __restrict__ wchange_w) {
    int bt = blockIdx.x;                  // b*T + t
    const int* xr = x + (size_t)bt * (MI + 1);
    __shared__ int s_items[MI];
    __shared__ int s_flag;
    int tid = threadIdx.x;
    if (tid < MI) s_items[tid] = xr[tid];
    if (tid == MI) s_flag = xr[MI];
    __syncthreads();

    if (tid < En) {
        float acc = 0.f;
        int cnt = 0;
        #pragma unroll
        for (int i = 0; i < MI; i++) {
            int it = s_items[i];
            cnt += (it != 0);
            acc += encode_w[(size_t)it * En + tid];   // row 0 is all-zero
        }
        float inv = 1.f / (float)(cnt > 0 ? cnt : 1);
        g_seq[(size_t)bt * Dn + tid] = acc * inv;
    } else if (tid < Dn) {
        g_seq[(size_t)bt * Dn + tid] = wchange_w[s_flag * 16 + (tid - En)];
    }
}

// ---------------------------------------------------------------------------
// 2) generic C[M,N] = A[M,144] * Bm[N,144]^T + bias   (tiled 64x64, 256 thr)
//    used for gi (N=432) and fc (N=128). M multiple of 64.
// ---------------------------------------------------------------------------
__global__ void __launch_bounds__(256)
gemm_tn(const float* __restrict__ A, const float* __restrict__ Bm,
        const float* __restrict__ bias, float* __restrict__ C, int N) {
    extern __shared__ float sm[];
    float* Ast = sm;              // [144][65]  (k-major, padded)
    float* Bst = sm + KD * 65;    // [144][65]

    int tid = threadIdx.x;
    int tx = tid & 15, ty = tid >> 4;
    int m0 = blockIdx.y * 64, n0 = blockIdx.x * 64;

    for (int idx = tid; idx < 64 * KD; idx += 256) {
        int mm = idx / KD, kk = idx - mm * KD;
        Ast[kk * 65 + mm] = A[(size_t)(m0 + mm) * KD + kk];
    }
    for (int idx = tid; idx < 64 * KD; idx += 256) {
        int nn = idx / KD, kk = idx - nn * KD;
        Bst[kk * 65 + nn] = (n0 + nn < N) ? Bm[(size_t)(n0 + nn) * KD + kk] : 0.f;
    }
    __syncthreads();

    float c[4][4];
    #pragma unroll
    for (int i = 0; i < 4; i++)
        #pragma unroll
        for (int j = 0; j < 4; j++) c[i][j] = 0.f;

    #pragma unroll 8
    for (int k = 0; k < KD; k++) {
        float a[4], b[4];
        #pragma unroll
        for (int i = 0; i < 4; i++) a[i] = Ast[k * 65 + ty + 16 * i];
        #pragma unroll
        for (int j = 0; j < 4; j++) b[j] = Bst[k * 65 + tx + 16 * j];
        #pragma unroll
        for (int i = 0; i < 4; i++)
            #pragma unroll
            for (int j = 0; j < 4; j++) c[i][j] += a[i] * b[j];
    }

    #pragma unroll
    for (int j = 0; j < 4; j++) {
        int n = n0 + tx + 16 * j;
        if (n < N) {
            float bv = bias[n];
            #pragma unroll
            for (int i = 0; i < 4; i++)
                C[(size_t)(m0 + ty + 16 * i) * N + n] = c[i][j] + bv;
        }
    }
}

// ---------------------------------------------------------------------------
// 3) GRU recurrence: one CTA per batch element, 432 threads = one gate row
//    each. w_hh row j: k<96 in registers (persistent across 50 steps),
//    k>=96 in smem (k-major, lane-consecutive -> conflict-free).
// ---------------------------------------------------------------------------
__global__ void __launch_bounds__(G3, 1)
gru_kernel(const float* __restrict__ w_hh, const float* __restrict__ b_hh,
           const float* __restrict__ hidden, float* __restrict__ out) {
    extern __shared__ float sm[];
    float* s_wt  = sm;                 // [KS][432]
    float* s_h   = sm + KS * G3;       // [144]  (16B aligned)
    float* s_A   = s_h + Dn;           // [432] gate pre-activations
    float* s_gin = s_A + G3;           // [144] i_n stash

    int b = blockIdx.x;
    int j = threadIdx.x;

    // persistent weight registers for k in [0,96)
    float wreg[CREG];
    const float* wrow = w_hh + (size_t)j * KD;
    #pragma unroll
    for (int k = 0; k < CREG; k++) wreg[k] = wrow[k];
    // smem tail for k in [96,144)
    #pragma unroll
    for (int kk = 0; kk < KS; kk++) s_wt[kk * G3 + j] = wrow[CREG + kk];

    if (j < Dn) s_h[j] = hidden[(size_t)b * Dn + j];
    float bias = b_hh[j];
    __syncthreads();

    const float* giB = g_gi + (size_t)b * Tn * G3;
    float* hsB       = g_hseq + (size_t)b * Tn * Dn;
    const float4* h4 = reinterpret_cast<const float4*>(s_h);

    for (int t = 0; t < Tn; t++) {
        float gi_j = giB[t * G3 + j];
        float acc = bias;
        #pragma unroll
        for (int q = 0; q < CREG / 4; q++) {
            float4 h = h4[q];
            acc += wreg[4 * q + 0] * h.x;
            acc += wreg[4 * q + 1] * h.y;
            acc += wreg[4 * q + 2] * h.z;
            acc += wreg[4 * q + 3] * h.w;
        }
        #pragma unroll
        for (int q = 0; q < KS / 4; q++) {
            float4 h = h4[CREG / 4 + q];
            acc += s_wt[(4 * q + 0) * G3 + j] * h.x;
            acc += s_wt[(4 * q + 1) * G3 + j] * h.y;
            acc += s_wt[(4 * q + 2) * G3 + j] * h.z;
            acc += s_wt[(4 * q + 3) * G3 + j] * h.w;
        }

        if (j < 2 * Dn) {
            s_A[j] = gi_j + acc;               // r, z pre-activations
        } else {
            s_A[j] = acc;                      // h_n (needs r multiply)
            s_gin[j - 2 * Dn] = gi_j;          // i_n
        }
        __syncthreads();

        if (j < Dn) {
            float r = 1.f / (1.f + expf(-s_A[j]));
            float z = 1.f / (1.f + expf(-s_A[j + Dn]));
            float n = tanhf(s_gin[j] + r * s_A[j + 2 * Dn]);
            float hn = (1.f - z) * n + z * s_h[j];
            s_h[j] = hn;                       // only thread j touches s_h[j]
            hsB[t * Dn + j] = hn;
        }
        __syncthreads();
    }

    if (j < Dn) out[(size_t)Bn * Tn * En + (size_t)b * Dn + j] = s_h[j];
}

// ---------------------------------------------------------------------------
extern "C" void kernel_launch(void* const* d_in, const int* in_sizes, int n_in,
                              void* d_out, int out_size) {
    const int*   x        = (const int*)  d_in[0];
    // d_in[1] = lengths (int64) -- all == T, unused
    const float* hidden   = (const float*)d_in[2];
    const float* encode_w = (const float*)d_in[3];
    const float* wchange  = (const float*)d_in[4];
    const float* w_ih     = (const float*)d_in[5];
    const float* w_hh     = (const float*)d_in[6];
    const float* b_ih     = (const float*)d_in[7];
    const float* b_hh     = (const float*)d_in[8];
    const float* fc_w     = (const float*)d_in[9];
    const float* fc_b     = (const float*)d_in[10];
    float* out = (float*)d_out;

    float *p_seq, *p_gi, *p_hseq;
    cudaGetSymbolAddress((void**)&p_seq,  g_seq);
    cudaGetSymbolAddress((void**)&p_gi,   g_gi);
    cudaGetSymbolAddress((void**)&p_hseq, g_hseq);

    const int gemm_smem = 2 * KD * 65 * 4;                      // 74880 B
    const int gru_smem  = (KS * G3 + Dn + G3 + Dn) * 4;         // 85824 B
    cudaFuncSetAttribute(gemm_tn,    cudaFuncAttributeMaxDynamicSharedMemorySize, gemm_smem);
    cudaFuncSetAttribute(gru_kernel, cudaFuncAttributeMaxDynamicSharedMemorySize, gru_smem);

    // 1) embed
    embed_kernel<<<Bn * Tn, 160>>>(x, encode_w, wchange);

    // 2) gi = seq @ w_ih^T + b_ih   (6400 x 432)
    {
        dim3 grid((G3 + 63) / 64, (Bn * Tn) / 64);
        gemm_tn<<<grid, 256, gemm_smem>>>(p_seq, w_ih, b_ih, p_gi, G3);
    }

    // 3) GRU recurrence (one CTA per batch row), writes h_last to out tail
    gru_kernel<<<Bn, G3, gru_smem>>>(w_hh, b_hh, hidden, out);

    // 4) dynamic_user = hseq @ fc_w^T + fc_b  (6400 x 128) -> out head
    {
        dim3 grid(En / 64, (Bn * Tn) / 64);
        gemm_tn<<<grid, 256, gemm_smem>>>(p_hseq, fc_w, fc_b, out, En);
    }
}